// round 3
// baseline (speedup 1.0000x reference)
#include <cuda_runtime.h>
#include <cuda_bf16.h>

// SAR-ADC true-quantization: x[500000,24] f32, W[10] f32 ->
//   q[500000,24] f32  (first 12,000,000 floats of d_out)
//   Q[500000,24,4] f32 (next 48,000,000 floats of d_out)
//
// Latency-bound fix: 16 elements/thread, 4 front-batched float4 loads
// (MLP_p1=4), 4 independent SAR chains for ILP, 20 streaming STG.128.

#define LENGTH_ 500000
#define NADC_   24
#define NTOT_   (LENGTH_ * NADC_)    // 12,000,000
#define NELEM_PER_THREAD 16
#define NT_    (NTOT_ / NELEM_PER_THREAD)  // 750,000 threads

__device__ __forceinline__ float sar_sign(float v) {
    float t = v + 1e-30f;
    return (t > 0.0f) ? 1.0f : ((t < 0.0f) ? -1.0f : 0.0f);
}

__global__ __launch_bounds__(256, 4)
void sar_quant_kernel(const float4* __restrict__ x4,
                      const float*  __restrict__ W,
                      float4* __restrict__ q4,
                      float4* __restrict__ Qout) {
    int i = blockIdx.x * blockDim.x + threadIdx.x;
    if (i >= NT_) return;

    // Front-batch all 4 input vectors: MLP_p1 = 4.
    const float4* xp = x4 + 4 * (size_t)i;
    float4 xv0 = __ldcs(xp + 0);
    float4 xv1 = __ldcs(xp + 1);
    float4 xv2 = __ldcs(xp + 2);
    float4 xv3 = __ldcs(xp + 3);

    const float VR = 1.8f / 16.0f;   // LSB voltage; VREF == VR
    // Weight walk m = 9..0, scaled by VR. b_k = (Q_k+1)*0.5 carries the 0.5.
    const float t3  = W[9] * VR;
    const float t2  = W[8] * VR;
    const float c23 = W[7] * VR;
    const float t1  = W[6] * VR;
    const float c12 = W[5] * VR;
    const float c13 = W[4] * VR;
    const float t0  = W[3] * VR;
    const float c01 = W[2] * VR;
    const float c02 = W[1] * VR;
    const float c03 = W[0] * VR;

    float4* Qp = Qout + 16 * (size_t)i;
    float4* qp = q4   + 4  * (size_t)i;

    float4 xs[4] = {xv0, xv1, xv2, xv3};
    #pragma unroll
    for (int g = 0; g < 4; g++) {
        const float xe[4] = {xs[g].x, xs[g].y, xs[g].z, xs[g].w};
        float qo[4];
        #pragma unroll
        for (int e = 0; e < 4; e++) {
            float xx = xe[e];
            float Q3 = sar_sign(xx - t3);
            float b3 = (Q3 + 1.0f) * 0.5f;
            float Q2 = sar_sign(xx - (t2 + b3 * c23));
            float b2 = (Q2 + 1.0f) * 0.5f;
            float Q1 = sar_sign(xx - (t1 + b2 * c12 + b3 * c13));
            float b1 = (Q1 + 1.0f) * 0.5f;
            float Q0 = sar_sign(xx - (t0 + b1 * c01 + b2 * c02 + b3 * c03));
            float b0 = (Q0 + 1.0f) * 0.5f;
            qo[e] = VR * (b0 + 2.0f * b1 + 4.0f * b2 + 8.0f * b3);
            __stcs(Qp + 4 * g + e, make_float4(Q0, Q1, Q2, Q3));
        }
        __stcs(qp + g, make_float4(qo[0], qo[1], qo[2], qo[3]));
    }
}

extern "C" void kernel_launch(void* const* d_in, const int* in_sizes, int n_in,
                              void* d_out, int out_size) {
    const float4* x4 = (const float4*)d_in[0];
    const float*  W  = (const float*)d_in[1];
    float* out = (float*)d_out;
    float4* q4   = (float4*)out;                   // 12,000,000 floats
    float4* Qout = (float4*)(out + (size_t)NTOT_); // 48,000,000 floats

    const int threads = 256;
    const int blocks  = (NT_ + threads - 1) / threads;
    sar_quant_kernel<<<blocks, threads>>>(x4, W, q4, Qout);
}

// round 6
// speedup vs baseline: 1.0343x; 1.0343x over previous
#include <cuda_runtime.h>
#include <cuda_bf16.h>

// SAR-ADC true-quantization: x[500000,24] f32, W[10] f32 ->
//   q[500000,24] f32  (first 12,000,000 floats of d_out)
//   Q[500000,24,4] f32 (next 48,000,000 floats of d_out)
//
// R4: 8 elems/thread, 2 front-batched LDG.128 (MLP=2), vectorized W loads
// (3 LDGs instead of 10 scalars), default stores, high occupancy.

#define LENGTH_ 500000
#define NADC_   24
#define NTOT_   (LENGTH_ * NADC_)    // 12,000,000
#define NELEM_  8
#define NT_     (NTOT_ / NELEM_)     // 1,500,000 threads

__device__ __forceinline__ float sar_sign(float v) {
    float t = v + 1e-30f;
    return (t > 0.0f) ? 1.0f : ((t < 0.0f) ? -1.0f : 0.0f);
}

__global__ __launch_bounds__(256)
void sar_quant_kernel(const float4* __restrict__ x4,
                      const float*  __restrict__ W,
                      float4* __restrict__ q4,
                      float4* __restrict__ Qout) {
    int i = blockIdx.x * blockDim.x + threadIdx.x;
    if (i >= NT_) return;

    // Front-batch the 2 input vectors (MLP_p1 = 2).
    const float4* xp = x4 + 2 * (size_t)i;
    float4 xv0 = xp[0];
    float4 xv1 = xp[1];

    // Vectorized weight load: 3 L1-broadcast LDGs instead of 10 scalars.
    const float4 wA = __ldg((const float4*)W);       // W[0..3]
    const float4 wB = __ldg(((const float4*)W) + 1); // W[4..7]
    const float2 wC = __ldg((const float2*)(W + 8)); // W[8..9]

    const float VR = 1.8f / 16.0f;   // LSB voltage; VREF == VR
    // Weight walk m = 9..0, scaled by VR. b_k = (Q_k+1)*0.5 carries the 0.5.
    const float t3  = wC.y * VR;   // W[9]
    const float t2  = wC.x * VR;   // W[8]
    const float c23 = wB.w * VR;   // W[7]
    const float t1  = wB.z * VR;   // W[6]
    const float c12 = wB.y * VR;   // W[5]
    const float c13 = wB.x * VR;   // W[4]
    const float t0  = wA.w * VR;   // W[3]
    const float c01 = wA.z * VR;   // W[2]
    const float c02 = wA.y * VR;   // W[1]
    const float c03 = wA.x * VR;   // W[0]

    float4* Qp = Qout + 8 * (size_t)i;
    float4* qp = q4   + 2 * (size_t)i;

    float4 xs[2] = {xv0, xv1};
    #pragma unroll
    for (int g = 0; g < 2; g++) {
        const float xe[4] = {xs[g].x, xs[g].y, xs[g].z, xs[g].w};
        float qo[4];
        #pragma unroll
        for (int e = 0; e < 4; e++) {
            float xx = xe[e];
            float Q3 = sar_sign(xx - t3);
            float b3 = (Q3 + 1.0f) * 0.5f;
            float Q2 = sar_sign(xx - (t2 + b3 * c23));
            float b2 = (Q2 + 1.0f) * 0.5f;
            float Q1 = sar_sign(xx - (t1 + b2 * c12 + b3 * c13));
            float b1 = (Q1 + 1.0f) * 0.5f;
            float Q0 = sar_sign(xx - (t0 + b1 * c01 + b2 * c02 + b3 * c03));
            float b0 = (Q0 + 1.0f) * 0.5f;
            qo[e] = VR * (b0 + 2.0f * b1 + 4.0f * b2 + 8.0f * b3);
            Qp[4 * g + e] = make_float4(Q0, Q1, Q2, Q3);
        }
        qp[g] = make_float4(qo[0], qo[1], qo[2], qo[3]);
    }
}

extern "C" void kernel_launch(void* const* d_in, const int* in_sizes, int n_in,
                              void* d_out, int out_size) {
    const float4* x4 = (const float4*)d_in[0];
    const float*  W  = (const float*)d_in[1];
    float* out = (float*)d_out;
    float4* q4   = (float4*)out;                   // 12,000,000 floats
    float4* Qout = (float4*)(out + (size_t)NTOT_); // 48,000,000 floats

    const int threads = 256;
    const int blocks  = (NT_ + threads - 1) / threads;
    sar_quant_kernel<<<blocks, threads>>>(x4, W, q4, Qout);
}

// round 7
// speedup vs baseline: 2.0514x; 1.9833x over previous
#include <cuda_runtime.h>
#include <cuda_bf16.h>

// SAR-ADC true-quantization: x[500000,24] f32, W[10] f32 ->
//   q[500000,24] f32  (first 12,000,000 floats of d_out)
//   Q[500000,24,4] f32 (next 48,000,000 floats of d_out)
//
// R6: 1 element/thread, max TLP, every access stream perfectly coalesced:
//   x: LDG.32 lane-stride 4B; q: STG.32 lane-stride 4B;
//   Q: one STG.128 per thread, lane-stride 16B (512B contiguous per warp).

#define LENGTH_ 500000
#define NADC_   24
#define NTOT_   (LENGTH_ * NADC_)    // 12,000,000

__device__ __forceinline__ float sar_sign(float v) {
    float t = v + 1e-30f;
    return (t > 0.0f) ? 1.0f : ((t < 0.0f) ? -1.0f : 0.0f);
}

__global__ __launch_bounds__(256)
void sar_quant_kernel(const float* __restrict__ x,
                      const float* __restrict__ W,
                      float* __restrict__ q,
                      float4* __restrict__ Qout) {
    int i = blockIdx.x * blockDim.x + threadIdx.x;
    if (i >= NTOT_) return;

    float xx = x[i];

    // Vectorized weight load: 3 broadcast LDGs.
    const float4 wA = __ldg((const float4*)W);       // W[0..3]
    const float4 wB = __ldg(((const float4*)W) + 1); // W[4..7]
    const float2 wC = __ldg((const float2*)(W + 8)); // W[8..9]

    const float VR = 1.8f / 16.0f;   // LSB voltage; VREF == VR
    // Weight walk m = 9..0, scaled by VR. b_k = (Q_k+1)*0.5 carries the 0.5.
    const float t3  = wC.y * VR;   // W[9]
    const float t2  = wC.x * VR;   // W[8]
    const float c23 = wB.w * VR;   // W[7]
    const float t1  = wB.z * VR;   // W[6]
    const float c12 = wB.y * VR;   // W[5]
    const float c13 = wB.x * VR;   // W[4]
    const float t0  = wA.w * VR;   // W[3]
    const float c01 = wA.z * VR;   // W[2]
    const float c02 = wA.y * VR;   // W[1]
    const float c03 = wA.x * VR;   // W[0]

    float Q3 = sar_sign(xx - t3);
    float b3 = (Q3 + 1.0f) * 0.5f;
    float Q2 = sar_sign(xx - (t2 + b3 * c23));
    float b2 = (Q2 + 1.0f) * 0.5f;
    float Q1 = sar_sign(xx - (t1 + b2 * c12 + b3 * c13));
    float b1 = (Q1 + 1.0f) * 0.5f;
    float Q0 = sar_sign(xx - (t0 + b1 * c01 + b2 * c02 + b3 * c03));
    float b0 = (Q0 + 1.0f) * 0.5f;

    q[i] = VR * (b0 + 2.0f * b1 + 4.0f * b2 + 8.0f * b3);
    Qout[i] = make_float4(Q0, Q1, Q2, Q3);
}

extern "C" void kernel_launch(void* const* d_in, const int* in_sizes, int n_in,
                              void* d_out, int out_size) {
    const float* x = (const float*)d_in[0];
    const float* W = (const float*)d_in[1];
    float* out = (float*)d_out;
    float*  q    = out;                              // 12,000,000 floats
    float4* Qout = (float4*)(out + (size_t)NTOT_);   // 48,000,000 floats

    const int threads = 256;
    const int blocks  = (NTOT_ + threads - 1) / threads;
    sar_quant_kernel<<<blocks, threads>>>(x, W, q, Qout);
}

// round 13
// speedup vs baseline: 2.3250x; 1.1334x over previous
#include <cuda_runtime.h>
#include <cuda_bf16.h>

// SAR-ADC true-quantization: x[500000,24] f32, W[10] f32 ->
//   q[500000,24] f32  (first 12,000,000 floats of d_out)
//   Q[500000,24,4] f32 (next 48,000,000 floats of d_out)
//
// R13 (= R7 re-bench after infra failure): grid-stride pair.
// Thread t handles elements t and t + NTOT/2:
//  - both LDG.32 front-batched (MLP=2), two independent SAR chains (ILP=2)
//  - every load/store instruction keeps perfect lane coalescing
//    (x/q: 4B lane stride; Q: STG.128 with 16B lane stride = 512B/warp)
//  - sign(v + 1e-30) == (v >= 0 ? +1 : -1) exactly in fp32 for this data
//    (v is a difference of O(0.1) values: either 0 -> delta forces +1,
//     or |v| >= ~1ulp(0.1) >> 1e-30; negative subnormals unreachable).

#define LENGTH_ 500000
#define NADC_   24
#define NTOT_   (LENGTH_ * NADC_)    // 12,000,000
#define HALF_   (NTOT_ / 2)          // 6,000,000

__global__ __launch_bounds__(256)
void sar_quant_kernel(const float* __restrict__ x,
                      const float* __restrict__ W,
                      float* __restrict__ q,
                      float4* __restrict__ Qout) {
    int i = blockIdx.x * blockDim.x + threadIdx.x;
    if (i >= HALF_) return;
    int j = i + HALF_;

    // Front-batch both input loads (independent, MLP=2).
    float xa = x[i];
    float xb = x[j];

    // Vectorized weight load: 3 broadcast LDGs.
    const float4 wA = __ldg((const float4*)W);       // W[0..3]
    const float4 wB = __ldg(((const float4*)W) + 1); // W[4..7]
    const float2 wC = __ldg((const float2*)(W + 8)); // W[8..9]

    const float VR = 1.8f / 16.0f;   // LSB voltage; VREF == VR
    // Weight walk m = 9..0, scaled by VR. b_k carries the 0.5 of (Q+1)/2.
    const float t3  = wC.y * VR;   // W[9]
    const float t2  = wC.x * VR;   // W[8]
    const float c23 = wB.w * VR;   // W[7]
    const float t1  = wB.z * VR;   // W[6]
    const float c12 = wB.y * VR;   // W[5]
    const float c13 = wB.x * VR;   // W[4]
    const float t0  = wA.w * VR;   // W[3]
    const float c01 = wA.z * VR;   // W[2]
    const float c02 = wA.y * VR;   // W[1]
    const float c03 = wA.x * VR;   // W[0]

    float qa, qb;
    float4 Qa, Qb;

    #pragma unroll
    for (int g = 0; g < 2; g++) {
        float xx = (g == 0) ? xa : xb;

        bool p3 = (xx - t3) >= 0.0f;
        float b3 = p3 ? 1.0f : 0.0f;
        bool p2 = (xx - (t2 + b3 * c23)) >= 0.0f;
        float b2 = p2 ? 1.0f : 0.0f;
        bool p1 = (xx - (t1 + b2 * c12 + b3 * c13)) >= 0.0f;
        float b1 = p1 ? 1.0f : 0.0f;
        bool p0 = (xx - (t0 + b1 * c01 + b2 * c02 + b3 * c03)) >= 0.0f;
        float b0 = p0 ? 1.0f : 0.0f;

        float qv = VR * (b0 + 2.0f * b1 + 4.0f * b2 + 8.0f * b3);
        float4 Qv = make_float4(p0 ? 1.0f : -1.0f,
                                p1 ? 1.0f : -1.0f,
                                p2 ? 1.0f : -1.0f,
                                p3 ? 1.0f : -1.0f);
        if (g == 0) { qa = qv; Qa = Qv; }
        else        { qb = qv; Qb = Qv; }
    }

    q[i] = qa;
    q[j] = qb;
    Qout[i] = Qa;
    Qout[j] = Qb;
}

extern "C" void kernel_launch(void* const* d_in, const int* in_sizes, int n_in,
                              void* d_out, int out_size) {
    const float* x = (const float*)d_in[0];
    const float* W = (const float*)d_in[1];
    float* out = (float*)d_out;
    float*  q    = out;                              // 12,000,000 floats
    float4* Qout = (float4*)(out + (size_t)NTOT_);   // 48,000,000 floats

    const int threads = 256;
    const int blocks  = (HALF_ + threads - 1) / threads;
    sar_quant_kernel<<<blocks, threads>>>(x, W, q, Qout);
}